// round 1
// baseline (speedup 1.0000x reference)
#include <cuda_runtime.h>
#include <math.h>

// Problem constants
#define Bc   8
#define Nc   1024
#define OBSc 64
#define HIDc 192
#define Hc   3
#define Dc   64
#define BHc  (Bc*Hc)

#define TI 128   // row tile in attention
#define TJ 64    // j tile in attention

// Scratch (device globals; no allocation allowed)
__device__ float g_Wh[BHc * Nc * Dc];   // (b,h,n,d) — reused per layer
__device__ float g_x [Bc * Nc * HIDc];  // inter-layer activations (b,n,hid)
__device__ float g_si[BHc * Nc];
__device__ float g_sj[BHc * Nc];

// ---------------------------------------------------------------------------
// Projection: Wh[b,h,n,d] = sum_k X[b,n,k] * W[h,k,d]
// Block computes 64 rows x 64 cols (one head per blockIdx.y).
// ---------------------------------------------------------------------------
template<int K, bool FROM_GX>
__global__ __launch_bounds__(256) void proj_kernel(const float* __restrict__ Xe,
                                                   const float* __restrict__ W)
{
    const float* X = FROM_GX ? (const float*)g_x : Xe;
    __shared__ float Ast[16][68];   // [kk][row]
    __shared__ float Bs [16][68];   // [kk][d]

    int tid = threadIdx.x;
    int tx = tid & 15, ty = tid >> 4;
    int row0 = blockIdx.x * 64;
    int hh = blockIdx.y;

    float acc[4][4] = {};

    for (int k0 = 0; k0 < K; k0 += 16) {
        // load A tile: 64 rows x 16 k (transposed into Ast)
        {
            int r  = tid >> 2;
            int kc = (tid & 3) * 4;
            float4 v = *(const float4*)&X[(size_t)(row0 + r) * K + k0 + kc];
            Ast[kc + 0][r] = v.x; Ast[kc + 1][r] = v.y;
            Ast[kc + 2][r] = v.z; Ast[kc + 3][r] = v.w;
        }
        // load B tile: 16 k x 64 d
        {
            int kk = tid >> 4;
            int c4 = (tid & 15) * 4;
            float4 v = *(const float4*)&W[(size_t)(hh * K + k0 + kk) * Dc + c4];
            *(float4*)&Bs[kk][c4] = v;
        }
        __syncthreads();
        #pragma unroll
        for (int kk = 0; kk < 16; kk++) {
            float a[4], b[4];
            #pragma unroll
            for (int i = 0; i < 4; i++) a[i] = Ast[kk][ty * 4 + i];
            #pragma unroll
            for (int j = 0; j < 4; j++) b[j] = Bs[kk][tx * 4 + j];
            #pragma unroll
            for (int i = 0; i < 4; i++)
                #pragma unroll
                for (int j = 0; j < 4; j++) acc[i][j] += a[i] * b[j];
        }
        __syncthreads();
    }

    #pragma unroll
    for (int i = 0; i < 4; i++) {
        int row = row0 + ty * 4 + i;
        int b = row >> 10, n = row & (Nc - 1);
        float4 v = make_float4(acc[i][0], acc[i][1], acc[i][2], acc[i][3]);
        *(float4*)&g_Wh[(size_t)((b * Hc + hh) * Nc + n) * Dc + tx * 4] = v;
    }
}

// ---------------------------------------------------------------------------
// Score vectors: s_i = Wh . a[:, :D], s_j = Wh . a[:, D:]  (one warp per row)
// ---------------------------------------------------------------------------
__global__ __launch_bounds__(256) void s_kernel(const float* __restrict__ a)
{
    int warp = (blockIdx.x * blockDim.x + threadIdx.x) >> 5;
    int lane = threadIdx.x & 31;
    if (warp >= BHc * Nc) return;
    int h = (warp / Nc) % Hc;
    const float* wh = &g_Wh[(size_t)warp * Dc];
    float w0 = wh[lane], w1 = wh[lane + 32];
    const float* ah = &a[h * 2 * Dc];
    float si = w0 * ah[lane]      + w1 * ah[lane + 32];
    float sj = w0 * ah[Dc + lane] + w1 * ah[Dc + lane + 32];
    #pragma unroll
    for (int o = 16; o; o >>= 1) {
        si += __shfl_xor_sync(0xffffffffu, si, o);
        sj += __shfl_xor_sync(0xffffffffu, sj, o);
    }
    if (lane == 0) { g_si[warp] = si; g_sj[warp] = sj; }
}

// ---------------------------------------------------------------------------
// Fused attention: out_row = softmax_j( mask(LReLU(s_i+s_j)) ) . Wh
// Factorized exp: no per-score MUFU.  Block: 128 rows x D=64 (full width).
// ---------------------------------------------------------------------------
template<bool ELU, bool TO_GX>
__global__ __launch_bounds__(256) void attn_kernel(const float* __restrict__ adj,
                                                   float* __restrict__ out_ext)
{
    extern __shared__ float sm[];
    float* sjv  = sm;             // Nc
    float* E1   = sjv + Nc;       // Nc
    float* E2   = E1  + Nc;       // Nc
    float* silv = E2  + Nc;       // TI
    float* A1   = silv + TI;      // TI
    float* A2   = A1   + TI;      // TI
    float* den  = A2   + TI;      // TI
    float* red  = den  + TI;      // 32
    float* Whs  = red  + 32;      // TJ*68
    float* Pt   = Whs  + TJ*68;   // TJ*132  (transposed P, padded)

    int tid = threadIdx.x;
    int bh  = blockIdx.y;
    int i0  = blockIdx.x * TI;

    const float* sj_g = &g_sj[(size_t)bh * Nc];
    const float* si_g = &g_si[(size_t)bh * Nc];
    const float* wh_g = &g_Wh[(size_t)bh * Nc * Dc];

    // ---- prologue: load s_j, global max, E1/E2, per-row A1/A2 ----
    float lmax = -3.0e38f;
    for (int j = tid; j < Nc; j += 256) {
        float v = sj_g[j];
        sjv[j] = v;
        lmax = fmaxf(lmax, v);
    }
    #pragma unroll
    for (int o = 16; o; o >>= 1) lmax = fmaxf(lmax, __shfl_xor_sync(0xffffffffu, lmax, o));
    if ((tid & 31) == 0) red[tid >> 5] = lmax;
    __syncthreads();
    float smax = red[0];
    #pragma unroll
    for (int w = 1; w < 8; w++) smax = fmaxf(smax, red[w]);

    for (int j = tid; j < Nc; j += 256) {
        float v = sjv[j];
        E1[j] = expf(v);
        E2[j] = expf(0.2f * v);
    }
    if (tid < TI) {
        float s = si_g[i0 + tid];
        silv[tid] = s;
        float e = s + smax;
        float m = e > 0.f ? e : 0.2f * e;     // exact row max for full adj; safe bound otherwise
        A1[tid] = expf(s - m);
        A2[tid] = expf(0.2f * s - m);
        den[tid] = 0.f;
    }
    __syncthreads();

    // producer mapping: each thread owns 1 row x 32 j per tile
    int prow = tid >> 1;
    int pj0  = (tid & 1) * 32;
    float psil = silv[prow];
    float pa1  = A1[prow];
    float pa2  = A2[prow];
    const float* adjrow = &adj[(size_t)(i0 + prow) * Nc];

    // consumer mapping: 16x16 threads, 8 rows x 4 cols per thread
    int ty = tid >> 4, tx = tid & 15;
    float acc[8][4] = {};

    for (int t = 0; t < Nc / TJ; t++) {
        int j0 = t * TJ;
        // load Wh tile (64 x 64) into smem
        {
            int r = tid >> 2;
            int c = (tid & 3) * 4;
            #pragma unroll
            for (int it = 0; it < 4; it++) {
                float4 v = *(const float4*)&wh_g[(size_t)(j0 + r) * Dc + c + it * 16];
                *(float4*)&Whs[r * 68 + c + it * 16] = v;
            }
        }
        // produce P tile (factorized exp, mask, partial denominator)
        {
            float dsum = 0.f;
            #pragma unroll
            for (int jo = 0; jo < 32; jo++) {
                int j = pj0 + jo;
                float sjx = sjv[j0 + j];
                float p = (psil + sjx) > 0.f ? pa1 * E1[j0 + j] : pa2 * E2[j0 + j];
                float av = adjrow[j0 + j];
                p = av > 0.f ? p : 0.f;
                Pt[j * 132 + prow] = p;
                dsum += p;
            }
            atomicAdd(&den[prow], dsum);
        }
        __syncthreads();
        // consume: acc += P^T tile @ Wh tile
        #pragma unroll
        for (int jj = 0; jj < TJ; jj++) {
            float4 p0 = *(float4*)&Pt[jj * 132 + ty * 8];
            float4 p1 = *(float4*)&Pt[jj * 132 + ty * 8 + 4];
            float4 v  = *(float4*)&Whs[jj * 68 + tx * 4];
            float pr[8] = {p0.x, p0.y, p0.z, p0.w, p1.x, p1.y, p1.z, p1.w};
            float vv[4] = {v.x, v.y, v.z, v.w};
            #pragma unroll
            for (int r = 0; r < 8; r++)
                #pragma unroll
                for (int c = 0; c < 4; c++)
                    acc[r][c] += pr[r] * vv[c];
        }
        __syncthreads();
    }

    // ---- epilogue: normalize, optional ELU, write concat layout ----
    int b = bh / Hc, h = bh % Hc;
    float* outp = TO_GX ? g_x : out_ext;
    #pragma unroll
    for (int r = 0; r < 8; r++) {
        int il = ty * 8 + r;
        float inv = 1.f / den[il];
        int n = i0 + il;
        float o[4];
        #pragma unroll
        for (int c = 0; c < 4; c++) {
            float v = acc[r][c] * inv;
            if (ELU) v = v > 0.f ? v : expm1f(v);
            o[c] = v;
        }
        float4 v4 = make_float4(o[0], o[1], o[2], o[3]);
        *(float4*)&outp[(size_t)(b * Nc + n) * HIDc + h * Dc + tx * 4] = v4;
    }
}

// ---------------------------------------------------------------------------
extern "C" void kernel_launch(void* const* d_in, const int* in_sizes, int n_in,
                              void* d_out, int out_size)
{
    const float* h   = (const float*)d_in[0];
    const float* adj = (const float*)d_in[1];
    const float* W1  = (const float*)d_in[2];
    const float* a1  = (const float*)d_in[3];
    const float* W2  = (const float*)d_in[4];
    const float* a2  = (const float*)d_in[5];
    float* out = (float*)d_out;

    const size_t shmem = (size_t)(3 * Nc + 4 * TI + 32 + TJ * 68 + TJ * 132) * sizeof(float);
    cudaFuncSetAttribute(attn_kernel<true,  true >, cudaFuncAttributeMaxDynamicSharedMemorySize, (int)shmem);
    cudaFuncSetAttribute(attn_kernel<false, false>, cudaFuncAttributeMaxDynamicSharedMemorySize, (int)shmem);

    dim3 projGrid(Bc * Nc / 64, Hc);
    dim3 attnGrid(Nc / TI, BHc);
    int sBlocks = (BHc * Nc) / 8;   // 8 warps per 256-thread block

    // Layer 1
    proj_kernel<OBSc, false><<<projGrid, 256>>>(h, W1);
    s_kernel<<<sBlocks, 256>>>(a1);
    attn_kernel<true, true><<<attnGrid, 256, shmem>>>(adj, nullptr);

    // Layer 2
    proj_kernel<HIDc, true><<<projGrid, 256>>>(nullptr, W2);
    s_kernel<<<sBlocks, 256>>>(a2);
    attn_kernel<false, false><<<attnGrid, 256, shmem>>>(adj, out);
}

// round 3
// speedup vs baseline: 3.3086x; 3.3086x over previous
#include <cuda_runtime.h>
#include <cstdint>
#include <math.h>

#define Bc   8
#define Nc   1024
#define OBSc 64
#define HIDc 192
#define Hc   3
#define Dc   64
#define BHc  (Bc*Hc)

#define LDA 36   // padded stride for A tiles (128 x 32)
#define LDB 72   // padded stride for B tiles (32 x 64)

// Scratch (device globals; no allocation allowed)
__device__ float g_Wh[BHc * Nc * Dc];   // (bh, n, d)
__device__ float g_x [Bc * Nc * HIDc];  // inter-layer activations
__device__ float g_si[BHc * Nc];
__device__ float g_sj[BHc * Nc];

__device__ __forceinline__ uint32_t tf32u(float x){   // round-to-nearest tf32
    uint32_t u; asm("cvt.rna.tf32.f32 %0, %1;" : "=r"(u) : "f"(x));
    return u;
}
__device__ __forceinline__ void mma8(float* d, uint32_t a0, uint32_t a1, uint32_t a2, uint32_t a3,
                                     uint32_t b0, uint32_t b1){
    asm volatile("mma.sync.aligned.m16n8k8.row.col.f32.tf32.tf32.f32 "
        "{%0,%1,%2,%3}, {%4,%5,%6,%7}, {%8,%9}, {%0,%1,%2,%3};"
        : "+f"(d[0]), "+f"(d[1]), "+f"(d[2]), "+f"(d[3])
        : "r"(a0), "r"(a1), "r"(a2), "r"(a3), "r"(b0), "r"(b1));
}

// Consumer: acc(16x64 per warp) += A_tile(128x32) @ B_tile(32x64)
__device__ __forceinline__ void mma_tile(float acc[8][4], const uint32_t* As, const uint32_t* Bs,
                                         int wr0, int g, int tig){
    #pragma unroll
    for (int ks = 0; ks < 4; ks++){
        int ka = ks * 8 + tig;
        uint32_t a0 = As[(wr0 + g    ) * LDA + ka    ];
        uint32_t a1 = As[(wr0 + g + 8) * LDA + ka    ];
        uint32_t a2 = As[(wr0 + g    ) * LDA + ka + 4];
        uint32_t a3 = As[(wr0 + g + 8) * LDA + ka + 4];
        #pragma unroll
        for (int nt = 0; nt < 8; nt++){
            uint32_t b0 = Bs[ ka      * LDB + nt * 8 + g];
            uint32_t b1 = Bs[(ka + 4) * LDB + nt * 8 + g];
            mma8(acc[nt], a0, a1, a2, a3, b0, b1);
        }
    }
}

// ---------------------------------------------------------------------------
// Projection (tf32 mma): Wh = X @ W[h]; fused epilogue emits s_i, s_j.
// Block 256 = 8 warps; tile 128 rows x 64 cols; K chunks of 32.
// ---------------------------------------------------------------------------
template<int K, bool FROM_GX>
__global__ __launch_bounds__(256) void proj_mma(const float* __restrict__ Xe,
                                                const float* __restrict__ W,
                                                const float* __restrict__ av)
{
    __shared__ uint32_t As[128 * LDA];
    __shared__ uint32_t Bs[32 * LDB];
    __shared__ float sa[128];

    int tid = threadIdx.x, lane = tid & 31, wid = tid >> 5;
    int g = lane >> 2, tig = lane & 3, wr0 = wid * 16;
    int row0 = blockIdx.x * 128, h = blockIdx.y;
    const float* X = FROM_GX ? (const float*)g_x : Xe;

    if (tid < 128) sa[tid] = av[h * 128 + tid];

    int ar = tid >> 1, ac = (tid & 1) * 16;   // A loader: row ar, k cols ac..ac+15
    int bk = tid >> 3, bd = (tid & 7) * 8;    // B loader: k row bk, d cols bd..bd+7

    float acc[8][4] = {};

    #pragma unroll 2
    for (int t = 0; t < K / 32; t++){
        __syncthreads();
        {
            const float* xp = &X[(size_t)(row0 + ar) * K + t * 32 + ac];
            #pragma unroll
            for (int q = 0; q < 4; q++){
                float4 v = *(const float4*)&xp[q * 4];
                As[ar * LDA + ac + q * 4 + 0] = tf32u(v.x);
                As[ar * LDA + ac + q * 4 + 1] = tf32u(v.y);
                As[ar * LDA + ac + q * 4 + 2] = tf32u(v.z);
                As[ar * LDA + ac + q * 4 + 3] = tf32u(v.w);
            }
            const float* wp = &W[(size_t)(h * K + t * 32 + bk) * Dc + bd];
            float4 w0 = *(const float4*)&wp[0];
            float4 w1 = *(const float4*)&wp[4];
            Bs[bk * LDB + bd + 0] = tf32u(w0.x); Bs[bk * LDB + bd + 1] = tf32u(w0.y);
            Bs[bk * LDB + bd + 2] = tf32u(w0.z); Bs[bk * LDB + bd + 3] = tf32u(w0.w);
            Bs[bk * LDB + bd + 4] = tf32u(w1.x); Bs[bk * LDB + bd + 5] = tf32u(w1.y);
            Bs[bk * LDB + bd + 6] = tf32u(w1.z); Bs[bk * LDB + bd + 7] = tf32u(w1.w);
        }
        __syncthreads();
        mma_tile(acc, As, Bs, wr0, g, tig);
    }

    // Epilogue: s_i/s_j dot products from fragments + Wh store.
    float si0 = 0.f, sj0 = 0.f, si1 = 0.f, sj1 = 0.f;
    #pragma unroll
    for (int nt = 0; nt < 8; nt++){
        #pragma unroll
        for (int c = 0; c < 2; c++){
            int col = nt * 8 + 2 * tig + c;
            float al = sa[col], ar2 = sa[64 + col];
            si0 += acc[nt][c] * al;      sj0 += acc[nt][c] * ar2;
            si1 += acc[nt][2 + c] * al;  sj1 += acc[nt][2 + c] * ar2;
        }
    }
    si0 += __shfl_xor_sync(0xffffffffu, si0, 1); si0 += __shfl_xor_sync(0xffffffffu, si0, 2);
    sj0 += __shfl_xor_sync(0xffffffffu, sj0, 1); sj0 += __shfl_xor_sync(0xffffffffu, sj0, 2);
    si1 += __shfl_xor_sync(0xffffffffu, si1, 1); si1 += __shfl_xor_sync(0xffffffffu, si1, 2);
    sj1 += __shfl_xor_sync(0xffffffffu, sj1, 1); sj1 += __shfl_xor_sync(0xffffffffu, sj1, 2);

    int r = row0 + wr0 + g;
    int b = r >> 10, n = r & (Nc - 1);
    int bh = b * Hc + h;
    if (tig == 0){
        g_si[(size_t)bh * Nc + n] = si0;     g_sj[(size_t)bh * Nc + n] = sj0;
        g_si[(size_t)bh * Nc + n + 8] = si1; g_sj[(size_t)bh * Nc + n + 8] = sj1;
    }
    float* wh0 = &g_Wh[((size_t)bh * Nc + n    ) * Dc];
    float* wh1 = &g_Wh[((size_t)bh * Nc + n + 8) * Dc];
    #pragma unroll
    for (int nt = 0; nt < 8; nt++){
        *(float2*)&wh0[nt * 8 + 2 * tig] = make_float2(acc[nt][0], acc[nt][1]);
        *(float2*)&wh1[nt * 8 + 2 * tig] = make_float2(acc[nt][2], acc[nt][3]);
    }
}

// ---------------------------------------------------------------------------
// Attention (tf32 mma): out = softmax(mask(LReLU(s_i+s_j))) @ Wh.
// Factorized exp; P tiles 128x32 -> mma vs Wh tiles 32x64.
// ---------------------------------------------------------------------------
template<bool ELU, bool TO_GX>
__global__ __launch_bounds__(256) void attn_mma(const float* __restrict__ adj,
                                                float* __restrict__ out_ext)
{
    __shared__ float sjv[Nc], E1[Nc], E2[Nc];
    __shared__ float sil[128], A1v[128], A2v[128], den[128], red[8];
    __shared__ uint32_t Ps[128 * LDA];
    __shared__ uint32_t Ws[32 * LDB];

    int tid = threadIdx.x, lane = tid & 31, wid = tid >> 5;
    int g = lane >> 2, tig = lane & 3, wr0 = wid * 16;
    int bh = blockIdx.y, i0 = blockIdx.x * 128;

    const float* sjg = &g_sj[(size_t)bh * Nc];
    const float* sig = &g_si[(size_t)bh * Nc];

    // Prologue: s_j, global max, E1/E2, per-row A1/A2.
    float lmax = -3.0e38f;
    for (int j = tid; j < Nc; j += 256){ float v = sjg[j]; sjv[j] = v; lmax = fmaxf(lmax, v); }
    #pragma unroll
    for (int o = 16; o; o >>= 1) lmax = fmaxf(lmax, __shfl_xor_sync(0xffffffffu, lmax, o));
    if (lane == 0) red[wid] = lmax;
    __syncthreads();
    float smax = red[0];
    #pragma unroll
    for (int w2 = 1; w2 < 8; w2++) smax = fmaxf(smax, red[w2]);
    for (int j = tid; j < Nc; j += 256){ float v = sjv[j]; E1[j] = expf(v); E2[j] = expf(0.2f * v); }
    if (tid < 128){
        float s = sig[i0 + tid]; sil[tid] = s;
        float e = s + smax; float m = e > 0.f ? e : 0.2f * e;   // exact row max bound
        A1v[tid] = expf(s - m); A2v[tid] = expf(0.2f * s - m);
    }
    __syncthreads();

    int pr = tid >> 1, pj = (tid & 1) * 16;        // producer: row pr, j cols pj..pj+15
    float psil = sil[pr], pa1 = A1v[pr], pa2 = A2v[pr];
    const float* adjrow = adj + (size_t)(i0 + pr) * Nc + pj;
    int bk = tid >> 3, bd = (tid & 7) * 8;         // Wh loader: j row bk, d cols bd..bd+7
    const float* whbase = &g_Wh[((size_t)bh * Nc + bk) * Dc + bd];

    float acc[8][4] = {};
    float dtot = 0.f;

    for (int t = 0; t < Nc / 32; t++){
        __syncthreads();
        int j0 = t * 32;
        // Wh tile
        {
            const float* wp = whbase + (size_t)j0 * Dc;
            float4 w0 = *(const float4*)&wp[0];
            float4 w1 = *(const float4*)&wp[4];
            Ws[bk * LDB + bd + 0] = tf32u(w0.x); Ws[bk * LDB + bd + 1] = tf32u(w0.y);
            Ws[bk * LDB + bd + 2] = tf32u(w0.z); Ws[bk * LDB + bd + 3] = tf32u(w0.w);
            Ws[bk * LDB + bd + 4] = tf32u(w1.x); Ws[bk * LDB + bd + 5] = tf32u(w1.y);
            Ws[bk * LDB + bd + 6] = tf32u(w1.z); Ws[bk * LDB + bd + 7] = tf32u(w1.w);
        }
        // P tile (factorized exp + mask) and running denominator
        #pragma unroll
        for (int q = 0; q < 4; q++){
            int j = pj + q * 4;
            float4 s4  = *(float4*)&sjv[j0 + j];
            float4 e14 = *(float4*)&E1 [j0 + j];
            float4 e24 = *(float4*)&E2 [j0 + j];
            float4 a4  = *(const float4*)&adjrow[j0 + q * 4];
            float p0 = (psil + s4.x > 0.f) ? pa1 * e14.x : pa2 * e24.x; if (!(a4.x > 0.f)) p0 = 0.f;
            float p1 = (psil + s4.y > 0.f) ? pa1 * e14.y : pa2 * e24.y; if (!(a4.y > 0.f)) p1 = 0.f;
            float p2 = (psil + s4.z > 0.f) ? pa1 * e14.z : pa2 * e24.z; if (!(a4.z > 0.f)) p2 = 0.f;
            float p3 = (psil + s4.w > 0.f) ? pa1 * e14.w : pa2 * e24.w; if (!(a4.w > 0.f)) p3 = 0.f;
            uint32_t u0 = tf32u(p0), u1 = tf32u(p1), u2 = tf32u(p2), u3 = tf32u(p3);
            dtot += (__uint_as_float(u0) + __uint_as_float(u1)) +
                    (__uint_as_float(u2) + __uint_as_float(u3));
            Ps[pr * LDA + j + 0] = u0; Ps[pr * LDA + j + 1] = u1;
            Ps[pr * LDA + j + 2] = u2; Ps[pr * LDA + j + 3] = u3;
        }
        __syncthreads();
        mma_tile(acc, Ps, Ws, wr0, g, tig);
    }

    // Denominator: pair-reduce (threads tid, tid^1 share row pr).
    dtot += __shfl_xor_sync(0xffffffffu, dtot, 1);
    if ((tid & 1) == 0) den[pr] = dtot;
    __syncthreads();

    // Epilogue: normalize (+ELU), write concat layout.
    int r0 = wr0 + g;
    float inv0 = 1.f / den[r0];
    float inv1 = 1.f / den[r0 + 8];
    int b = bh / Hc, hh = bh % Hc;
    float* op = TO_GX ? (float*)g_x : out_ext;
    int n = i0 + r0;
    float* o0 = &op[(size_t)(b * Nc + n    ) * HIDc + hh * Dc];
    float* o1 = &op[(size_t)(b * Nc + n + 8) * HIDc + hh * Dc];
    #pragma unroll
    for (int nt = 0; nt < 8; nt++){
        float v00 = acc[nt][0] * inv0, v01 = acc[nt][1] * inv0;
        float v10 = acc[nt][2] * inv1, v11 = acc[nt][3] * inv1;
        if (ELU){
            v00 = v00 > 0.f ? v00 : expm1f(v00);
            v01 = v01 > 0.f ? v01 : expm1f(v01);
            v10 = v10 > 0.f ? v10 : expm1f(v10);
            v11 = v11 > 0.f ? v11 : expm1f(v11);
        }
        *(float2*)&o0[nt * 8 + 2 * tig] = make_float2(v00, v01);
        *(float2*)&o1[nt * 8 + 2 * tig] = make_float2(v10, v11);
    }
}

// ---------------------------------------------------------------------------
extern "C" void kernel_launch(void* const* d_in, const int* in_sizes, int n_in,
                              void* d_out, int out_size)
{
    const float* h   = (const float*)d_in[0];
    const float* adj = (const float*)d_in[1];
    const float* W1  = (const float*)d_in[2];
    const float* a1  = (const float*)d_in[3];
    const float* W2  = (const float*)d_in[4];
    const float* a2  = (const float*)d_in[5];
    float* out = (float*)d_out;

    dim3 projGrid(Bc * Nc / 128, Hc);   // (64, 3)
    dim3 attnGrid(Nc / 128, BHc);       // (8, 24)

    proj_mma<OBSc, false><<<projGrid, 256>>>(h, W1, a1);
    attn_mma<true,  true ><<<attnGrid, 256>>>(adj, nullptr);
    proj_mma<HIDc, true ><<<projGrid, 256>>>(nullptr, W2, a2);
    attn_mma<false, false><<<attnGrid, 256>>>(adj, out);
}

// round 4
// speedup vs baseline: 3.3421x; 1.0101x over previous
#include <cuda_runtime.h>
#include <cstdint>
#include <math.h>

#define Bc   8
#define Nc   1024
#define OBSc 64
#define HIDc 192
#define Hc   3
#define Dc   64
#define BHc  (Bc*Hc)

#define LDA 36   // padded stride for A/P tiles (128 x 32)
#define LDB 72   // padded stride for B/W tiles (32 x 64)

// Scratch (device globals; no allocation allowed)
__device__ float g_Wh[BHc * Nc * Dc];   // (bh, n, d)
__device__ float g_x [Bc * Nc * HIDc];  // inter-layer activations
__device__ float g_si[BHc * Nc];
__device__ float g_sj[BHc * Nc];

__device__ __forceinline__ uint32_t tf32u(float x){   // round-to-nearest tf32
    uint32_t u; asm("cvt.rna.tf32.f32 %0, %1;" : "=r"(u) : "f"(x));
    return u;
}
__device__ __forceinline__ void mma8(float* d, uint32_t a0, uint32_t a1, uint32_t a2, uint32_t a3,
                                     uint32_t b0, uint32_t b1){
    asm volatile("mma.sync.aligned.m16n8k8.row.col.f32.tf32.tf32.f32 "
        "{%0,%1,%2,%3}, {%4,%5,%6,%7}, {%8,%9}, {%0,%1,%2,%3};"
        : "+f"(d[0]), "+f"(d[1]), "+f"(d[2]), "+f"(d[3])
        : "r"(a0), "r"(a1), "r"(a2), "r"(a3), "r"(b0), "r"(b1));
}

// Consumer: acc(16x64 per warp) += A_tile(128x32) @ B_tile(32x64)
__device__ __forceinline__ void mma_tile(float acc[8][4], const uint32_t* As, const uint32_t* Bs,
                                         int wr0, int g, int tig){
    #pragma unroll
    for (int ks = 0; ks < 4; ks++){
        int ka = ks * 8 + tig;
        uint32_t a0 = As[(wr0 + g    ) * LDA + ka    ];
        uint32_t a1 = As[(wr0 + g + 8) * LDA + ka    ];
        uint32_t a2 = As[(wr0 + g    ) * LDA + ka + 4];
        uint32_t a3 = As[(wr0 + g + 8) * LDA + ka + 4];
        #pragma unroll
        for (int nt = 0; nt < 8; nt++){
            uint32_t b0 = Bs[ ka      * LDB + nt * 8 + g];
            uint32_t b1 = Bs[(ka + 4) * LDB + nt * 8 + g];
            mma8(acc[nt], a0, a1, a2, a3, b0, b1);
        }
    }
}

// ---------------------------------------------------------------------------
// Projection (tf32 mma): Wh = X @ W[h]; fused epilogue emits s_i, s_j.
// ---------------------------------------------------------------------------
template<int K, bool FROM_GX>
__global__ __launch_bounds__(256) void proj_mma(const float* __restrict__ Xe,
                                                const float* __restrict__ W,
                                                const float* __restrict__ av)
{
    __shared__ uint32_t As[128 * LDA];
    __shared__ uint32_t Bs[32 * LDB];
    __shared__ float sa[128];

    int tid = threadIdx.x, lane = tid & 31, wid = tid >> 5;
    int g = lane >> 2, tig = lane & 3, wr0 = wid * 16;
    int row0 = blockIdx.x * 128, h = blockIdx.y;
    const float* X = FROM_GX ? (const float*)g_x : Xe;

    if (tid < 128) sa[tid] = av[h * 128 + tid];

    int ar = tid >> 1, ac = (tid & 1) * 16;   // A loader: row ar, k cols ac..ac+15
    int bk = tid >> 3, bd = (tid & 7) * 8;    // B loader: k row bk, d cols bd..bd+7

    float acc[8][4] = {};

    #pragma unroll 2
    for (int t = 0; t < K / 32; t++){
        __syncthreads();
        {
            const float* xp = &X[(size_t)(row0 + ar) * K + t * 32 + ac];
            #pragma unroll
            for (int q = 0; q < 4; q++){
                float4 v = *(const float4*)&xp[q * 4];
                As[ar * LDA + ac + q * 4 + 0] = tf32u(v.x);
                As[ar * LDA + ac + q * 4 + 1] = tf32u(v.y);
                As[ar * LDA + ac + q * 4 + 2] = tf32u(v.z);
                As[ar * LDA + ac + q * 4 + 3] = tf32u(v.w);
            }
            const float* wp = &W[(size_t)(h * K + t * 32 + bk) * Dc + bd];
            float4 w0 = *(const float4*)&wp[0];
            float4 w1 = *(const float4*)&wp[4];
            Bs[bk * LDB + bd + 0] = tf32u(w0.x); Bs[bk * LDB + bd + 1] = tf32u(w0.y);
            Bs[bk * LDB + bd + 2] = tf32u(w0.z); Bs[bk * LDB + bd + 3] = tf32u(w0.w);
            Bs[bk * LDB + bd + 4] = tf32u(w1.x); Bs[bk * LDB + bd + 5] = tf32u(w1.y);
            Bs[bk * LDB + bd + 6] = tf32u(w1.z); Bs[bk * LDB + bd + 7] = tf32u(w1.w);
        }
        __syncthreads();
        mma_tile(acc, As, Bs, wr0, g, tig);
    }

    // Epilogue: s_i/s_j dot products from fragments + Wh store.
    float si0 = 0.f, sj0 = 0.f, si1 = 0.f, sj1 = 0.f;
    #pragma unroll
    for (int nt = 0; nt < 8; nt++){
        #pragma unroll
        for (int c = 0; c < 2; c++){
            int col = nt * 8 + 2 * tig + c;
            float al = sa[col], ar2 = sa[64 + col];
            si0 += acc[nt][c] * al;      sj0 += acc[nt][c] * ar2;
            si1 += acc[nt][2 + c] * al;  sj1 += acc[nt][2 + c] * ar2;
        }
    }
    si0 += __shfl_xor_sync(0xffffffffu, si0, 1); si0 += __shfl_xor_sync(0xffffffffu, si0, 2);
    sj0 += __shfl_xor_sync(0xffffffffu, sj0, 1); sj0 += __shfl_xor_sync(0xffffffffu, sj0, 2);
    si1 += __shfl_xor_sync(0xffffffffu, si1, 1); si1 += __shfl_xor_sync(0xffffffffu, si1, 2);
    sj1 += __shfl_xor_sync(0xffffffffu, sj1, 1); sj1 += __shfl_xor_sync(0xffffffffu, sj1, 2);

    int r = row0 + wr0 + g;
    int b = r >> 10, n = r & (Nc - 1);
    int bh = b * Hc + h;
    if (tig == 0){
        g_si[(size_t)bh * Nc + n] = si0;     g_sj[(size_t)bh * Nc + n] = sj0;
        g_si[(size_t)bh * Nc + n + 8] = si1; g_sj[(size_t)bh * Nc + n + 8] = sj1;
    }
    float* wh0 = &g_Wh[((size_t)bh * Nc + n    ) * Dc];
    float* wh1 = &g_Wh[((size_t)bh * Nc + n + 8) * Dc];
    #pragma unroll
    for (int nt = 0; nt < 8; nt++){
        *(float2*)&wh0[nt * 8 + 2 * tig] = make_float2(acc[nt][0], acc[nt][1]);
        *(float2*)&wh1[nt * 8 + 2 * tig] = make_float2(acc[nt][2], acc[nt][3]);
    }
}

// ---------------------------------------------------------------------------
// Attention (tf32 mma, software-pipelined): out = softmax(...) @ Wh.
// Double-buffered P/W tiles, one barrier per iteration, reg-prefetch (t+2).
// ---------------------------------------------------------------------------
#define NTILE (Nc / 32)

template<bool ELU, bool TO_GX>
__global__ __launch_bounds__(256) void attn_mma(const float* __restrict__ adj,
                                                float* __restrict__ out_ext)
{
    extern __shared__ char smc[];
    float* sjv = (float*)smc;              // 1024
    float* E1  = sjv + Nc;                 // 1024
    float* E2  = E1  + Nc;                 // 1024
    float* sil = E2  + Nc;                 // 128
    float* A1v = sil + 128;
    float* A2v = A1v + 128;
    float* den = A2v + 128;
    float* red = den + 128;                // 32
    uint32_t* Ps = (uint32_t*)(red + 32);          // 2 x 128*LDA
    uint32_t* Ws = Ps + 2 * 128 * LDA;             // 2 x 32*LDB

    int tid = threadIdx.x, lane = tid & 31, wid = tid >> 5;
    int g = lane >> 2, tig = lane & 3, wr0 = wid * 16;
    int bh = blockIdx.y, i0 = blockIdx.x * 128;

    const float* sjg = &g_sj[(size_t)bh * Nc];
    const float* sig = &g_si[(size_t)bh * Nc];

    // ---- Prologue: s_j, global max, E1/E2, per-row A1/A2 ----
    float lmax = -3.0e38f;
    for (int j = tid; j < Nc; j += 256){ float v = sjg[j]; sjv[j] = v; lmax = fmaxf(lmax, v); }
    #pragma unroll
    for (int o = 16; o; o >>= 1) lmax = fmaxf(lmax, __shfl_xor_sync(0xffffffffu, lmax, o));
    if (lane == 0) red[wid] = lmax;
    __syncthreads();
    float smax = red[0];
    #pragma unroll
    for (int w2 = 1; w2 < 8; w2++) smax = fmaxf(smax, red[w2]);
    for (int j = tid; j < Nc; j += 256){ float v = sjv[j]; E1[j] = expf(v); E2[j] = expf(0.2f * v); }
    if (tid < 128){
        float s = sig[i0 + tid]; sil[tid] = s;
        float e = s + smax; float m = e > 0.f ? e : 0.2f * e;   // exact row-max bound
        A1v[tid] = expf(s - m); A2v[tid] = expf(0.2f * s - m);
    }
    __syncthreads();

    // Producer mapping: row pr, 16 j starting at pj within 32-j tile.
    int pr = tid >> 1, pj = (tid & 1) * 16;
    float psil = sil[pr], pa1 = A1v[pr], pa2 = A2v[pr];
    const float* adjrow = adj + (size_t)(i0 + pr) * Nc + pj;
    // W loader: j row bk (0..31), d cols bd..bd+7.
    int bk = tid >> 3, bd = (tid & 7) * 8;
    const float* whbase = &g_Wh[((size_t)bh * Nc + bk) * Dc + bd];

    float acc[8][4] = {};
    float dtot = 0.f;

    float4 adj_c[4], adj_n[4];
    float4 wh_c[2],  wh_n[2];

    // Preload tile 0 operands.
    #pragma unroll
    for (int q = 0; q < 4; q++) adj_c[q] = *(const float4*)&adjrow[q * 4];
    wh_c[0] = *(const float4*)&whbase[0];
    wh_c[1] = *(const float4*)&whbase[4];

    // produce(tile, buf): P + W tile stores from current regs.
    auto produce = [&](int t, int buf){
        int j0 = t * 32;
        uint32_t* Pb = Ps + buf * 128 * LDA;
        uint32_t* Wb = Ws + buf * 32 * LDB;
        #pragma unroll
        for (int q = 0; q < 4; q++){
            int j = pj + q * 4;
            float4 s4  = *(float4*)&sjv[j0 + j];
            float4 e14 = *(float4*)&E1 [j0 + j];
            float4 e24 = *(float4*)&E2 [j0 + j];
            float4 a4  = adj_c[q];
            float p0 = (psil + s4.x > 0.f) ? pa1 * e14.x : pa2 * e24.x; if (!(a4.x > 0.f)) p0 = 0.f;
            float p1 = (psil + s4.y > 0.f) ? pa1 * e14.y : pa2 * e24.y; if (!(a4.y > 0.f)) p1 = 0.f;
            float p2 = (psil + s4.z > 0.f) ? pa1 * e14.z : pa2 * e24.z; if (!(a4.z > 0.f)) p2 = 0.f;
            float p3 = (psil + s4.w > 0.f) ? pa1 * e14.w : pa2 * e24.w; if (!(a4.w > 0.f)) p3 = 0.f;
            uint32_t u0 = tf32u(p0), u1 = tf32u(p1), u2 = tf32u(p2), u3 = tf32u(p3);
            dtot += (__uint_as_float(u0) + __uint_as_float(u1)) +
                    (__uint_as_float(u2) + __uint_as_float(u3));
            Pb[pr * LDA + j + 0] = u0; Pb[pr * LDA + j + 1] = u1;
            Pb[pr * LDA + j + 2] = u2; Pb[pr * LDA + j + 3] = u3;
        }
        float4 w0 = wh_c[0], w1 = wh_c[1];
        Wb[bk * LDB + bd + 0] = tf32u(w0.x); Wb[bk * LDB + bd + 1] = tf32u(w0.y);
        Wb[bk * LDB + bd + 2] = tf32u(w0.z); Wb[bk * LDB + bd + 3] = tf32u(w0.w);
        Wb[bk * LDB + bd + 4] = tf32u(w1.x); Wb[bk * LDB + bd + 5] = tf32u(w1.y);
        Wb[bk * LDB + bd + 6] = tf32u(w1.z); Wb[bk * LDB + bd + 7] = tf32u(w1.w);
    };

    // Pipeline prologue: produce tile 0; fetch tile-1 regs.
    produce(0, 0);
    #pragma unroll
    for (int q = 0; q < 4; q++) adj_c[q] = *(const float4*)&adjrow[32 + q * 4];
    wh_c[0] = *(const float4*)&whbase[(size_t)32 * Dc];
    wh_c[1] = *(const float4*)&whbase[(size_t)32 * Dc + 4];
    __syncthreads();

    // Mainloop: one barrier per iteration; produce(t+1) overlaps mma(t).
    for (int t = 0; t < NTILE; t++){
        if (t + 2 < NTILE){
            int j0n = (t + 2) * 32;
            #pragma unroll
            for (int q = 0; q < 4; q++) adj_n[q] = *(const float4*)&adjrow[j0n + q * 4];
            wh_n[0] = *(const float4*)&whbase[(size_t)j0n * Dc];
            wh_n[1] = *(const float4*)&whbase[(size_t)j0n * Dc + 4];
        }
        if (t + 1 < NTILE) produce(t + 1, (t + 1) & 1);
        mma_tile(acc, Ps + (t & 1) * 128 * LDA, Ws + (t & 1) * 32 * LDB, wr0, g, tig);
        #pragma unroll
        for (int q = 0; q < 4; q++) adj_c[q] = adj_n[q];
        wh_c[0] = wh_n[0]; wh_c[1] = wh_n[1];
        __syncthreads();
    }

    // Denominator: pair-reduce (threads tid, tid^1 share row pr).
    dtot += __shfl_xor_sync(0xffffffffu, dtot, 1);
    if ((tid & 1) == 0) den[pr] = dtot;
    __syncthreads();

    // Epilogue: normalize (+ELU), write concat layout.
    int r0 = wr0 + g;
    float inv0 = 1.f / den[r0];
    float inv1 = 1.f / den[r0 + 8];
    int b = bh / Hc, hh = bh % Hc;
    float* op = TO_GX ? (float*)g_x : out_ext;
    int n = i0 + r0;
    float* o0 = &op[(size_t)(b * Nc + n    ) * HIDc + hh * Dc];
    float* o1 = &op[(size_t)(b * Nc + n + 8) * HIDc + hh * Dc];
    #pragma unroll
    for (int nt = 0; nt < 8; nt++){
        float v00 = acc[nt][0] * inv0, v01 = acc[nt][1] * inv0;
        float v10 = acc[nt][2] * inv1, v11 = acc[nt][3] * inv1;
        if (ELU){
            v00 = v00 > 0.f ? v00 : expm1f(v00);
            v01 = v01 > 0.f ? v01 : expm1f(v01);
            v10 = v10 > 0.f ? v10 : expm1f(v10);
            v11 = v11 > 0.f ? v11 : expm1f(v11);
        }
        *(float2*)&o0[nt * 8 + 2 * tig] = make_float2(v00, v01);
        *(float2*)&o1[nt * 8 + 2 * tig] = make_float2(v10, v11);
    }
}

// ---------------------------------------------------------------------------
extern "C" void kernel_launch(void* const* d_in, const int* in_sizes, int n_in,
                              void* d_out, int out_size)
{
    const float* h   = (const float*)d_in[0];
    const float* adj = (const float*)d_in[1];
    const float* W1  = (const float*)d_in[2];
    const float* a1  = (const float*)d_in[3];
    const float* W2  = (const float*)d_in[4];
    const float* a2  = (const float*)d_in[5];
    float* out = (float*)d_out;

    const int attn_smem = (3 * Nc + 4 * 128 + 32) * 4 + 2 * 128 * LDA * 4 + 2 * 32 * LDB * 4;
    cudaFuncSetAttribute(attn_mma<true,  true >, cudaFuncAttributeMaxDynamicSharedMemorySize, attn_smem);
    cudaFuncSetAttribute(attn_mma<false, false>, cudaFuncAttributeMaxDynamicSharedMemorySize, attn_smem);

    dim3 projGrid(Bc * Nc / 128, Hc);   // (64, 3)
    dim3 attnGrid(Nc / 128, BHc);       // (8, 24)

    proj_mma<OBSc, false><<<projGrid, 256>>>(h, W1, a1);
    attn_mma<true,  true ><<<attnGrid, 256, attn_smem>>>(adj, nullptr);
    proj_mma<HIDc, true ><<<projGrid, 256>>>(nullptr, W2, a2);
    attn_mma<false, false><<<attnGrid, 256, attn_smem>>>(adj, out);
}

// round 6
// speedup vs baseline: 3.7051x; 1.1086x over previous
#include <cuda_runtime.h>
#include <cstdint>
#include <math.h>

#define Bc   8
#define Nc   1024
#define OBSc 64
#define HIDc 192
#define Hc   3
#define Dc   64
#define BHc  (Bc*Hc)

#define LDA 36
#define LDB 72
#define NTILE (Nc / 32)

// Scratch (device globals; no allocation allowed)
__device__ float g_Wh[BHc * Nc * Dc];     // (bh, n, d)
__device__ float g_x [Bc * Nc * HIDc];    // inter-layer activations
__device__ float g_si[BHc * Nc];
__device__ float g_sj[BHc * Nc];
__device__ uint32_t g_adjbits[Nc * 32];   // adjacency bitmask, word w of row i

__device__ __forceinline__ uint32_t tf32u(float x){   // round-to-nearest tf32
    uint32_t u; asm("cvt.rna.tf32.f32 %0, %1;" : "=r"(u) : "f"(x));
    return u;
}
__device__ __forceinline__ void mma8(float* d, uint32_t a0, uint32_t a1, uint32_t a2, uint32_t a3,
                                     uint32_t b0, uint32_t b1){
    asm volatile("mma.sync.aligned.m16n8k8.row.col.f32.tf32.tf32.f32 "
        "{%0,%1,%2,%3}, {%4,%5,%6,%7}, {%8,%9}, {%0,%1,%2,%3};"
        : "+f"(d[0]), "+f"(d[1]), "+f"(d[2]), "+f"(d[3])
        : "r"(a0), "r"(a1), "r"(a2), "r"(a3), "r"(b0), "r"(b1));
}

// ---------------------------------------------------------------------------
// Adjacency bitmask: bit l of word (i*32+w) = (adj[i][w*32+l] > 0)
// ---------------------------------------------------------------------------
__global__ __launch_bounds__(256) void adjbits_kernel(const float* __restrict__ adj)
{
    int w = (blockIdx.x * blockDim.x + threadIdx.x) >> 5;
    int lane = threadIdx.x & 31;
    if (w < Nc * 32){
        float v = adj[(size_t)w * 32 + lane];
        uint32_t m = __ballot_sync(0xffffffffu, v > 0.f);
        if (lane == 0) g_adjbits[w] = m;
    }
}

// ---------------------------------------------------------------------------
// Projection (tf32 mma): Wh = X @ W[h]; fused epilogue emits s_i, s_j.
// ---------------------------------------------------------------------------
template<int K, bool FROM_GX>
__global__ __launch_bounds__(256) void proj_mma(const float* __restrict__ Xe,
                                                const float* __restrict__ W,
                                                const float* __restrict__ av)
{
    __shared__ uint32_t As[128 * LDA];
    __shared__ uint32_t Bs[32 * LDB];
    __shared__ float sa[128];

    int tid = threadIdx.x, lane = tid & 31, wid = tid >> 5;
    int g = lane >> 2, tig = lane & 3, wr0 = wid * 16;
    int row0 = blockIdx.x * 128, h = blockIdx.y;
    const float* X = FROM_GX ? (const float*)g_x : Xe;

    if (tid < 128) sa[tid] = av[h * 128 + tid];

    int ar = tid >> 1, ac = (tid & 1) * 16;
    int bk = tid >> 3, bd = (tid & 7) * 8;

    float acc[8][4] = {};

    #pragma unroll 2
    for (int t = 0; t < K / 32; t++){
        __syncthreads();
        {
            const float* xp = &X[(size_t)(row0 + ar) * K + t * 32 + ac];
            #pragma unroll
            for (int q = 0; q < 4; q++){
                float4 v = *(const float4*)&xp[q * 4];
                As[ar * LDA + ac + q * 4 + 0] = tf32u(v.x);
                As[ar * LDA + ac + q * 4 + 1] = tf32u(v.y);
                As[ar * LDA + ac + q * 4 + 2] = tf32u(v.z);
                As[ar * LDA + ac + q * 4 + 3] = tf32u(v.w);
            }
            const float* wp = &W[(size_t)(h * K + t * 32 + bk) * Dc + bd];
            float4 w0 = *(const float4*)&wp[0];
            float4 w1 = *(const float4*)&wp[4];
            Bs[bk * LDB + bd + 0] = tf32u(w0.x); Bs[bk * LDB + bd + 1] = tf32u(w0.y);
            Bs[bk * LDB + bd + 2] = tf32u(w0.z); Bs[bk * LDB + bd + 3] = tf32u(w0.w);
            Bs[bk * LDB + bd + 4] = tf32u(w1.x); Bs[bk * LDB + bd + 5] = tf32u(w1.y);
            Bs[bk * LDB + bd + 6] = tf32u(w1.z); Bs[bk * LDB + bd + 7] = tf32u(w1.w);
        }
        __syncthreads();
        #pragma unroll
        for (int ks = 0; ks < 4; ks++){
            int ka = ks * 8 + tig;
            uint32_t a0 = As[(wr0 + g    ) * LDA + ka    ];
            uint32_t a1 = As[(wr0 + g + 8) * LDA + ka    ];
            uint32_t a2 = As[(wr0 + g    ) * LDA + ka + 4];
            uint32_t a3 = As[(wr0 + g + 8) * LDA + ka + 4];
            #pragma unroll
            for (int nt = 0; nt < 8; nt++){
                uint32_t b0 = Bs[ ka      * LDB + nt * 8 + g];
                uint32_t b1 = Bs[(ka + 4) * LDB + nt * 8 + g];
                mma8(acc[nt], a0, a1, a2, a3, b0, b1);
            }
        }
    }

    // Epilogue: s_i/s_j from fragments + Wh store.
    float si0 = 0.f, sj0 = 0.f, si1 = 0.f, sj1 = 0.f;
    #pragma unroll
    for (int nt = 0; nt < 8; nt++){
        #pragma unroll
        for (int c = 0; c < 2; c++){
            int col = nt * 8 + 2 * tig + c;
            float al = sa[col], ar2 = sa[64 + col];
            si0 += acc[nt][c] * al;      sj0 += acc[nt][c] * ar2;
            si1 += acc[nt][2 + c] * al;  sj1 += acc[nt][2 + c] * ar2;
        }
    }
    si0 += __shfl_xor_sync(0xffffffffu, si0, 1); si0 += __shfl_xor_sync(0xffffffffu, si0, 2);
    sj0 += __shfl_xor_sync(0xffffffffu, sj0, 1); sj0 += __shfl_xor_sync(0xffffffffu, sj0, 2);
    si1 += __shfl_xor_sync(0xffffffffu, si1, 1); si1 += __shfl_xor_sync(0xffffffffu, si1, 2);
    sj1 += __shfl_xor_sync(0xffffffffu, sj1, 1); sj1 += __shfl_xor_sync(0xffffffffu, sj1, 2);

    int r = row0 + wr0 + g;
    int b = r >> 10, n = r & (Nc - 1);
    int bh = b * Hc + h;
    if (tig == 0){
        g_si[(size_t)bh * Nc + n] = si0;     g_sj[(size_t)bh * Nc + n] = sj0;
        g_si[(size_t)bh * Nc + n + 8] = si1; g_sj[(size_t)bh * Nc + n + 8] = sj1;
    }
    float* wh0 = &g_Wh[((size_t)bh * Nc + n    ) * Dc];
    float* wh1 = &g_Wh[((size_t)bh * Nc + n + 8) * Dc];
    #pragma unroll
    for (int nt = 0; nt < 8; nt++){
        *(float2*)&wh0[nt * 8 + 2 * tig] = make_float2(acc[nt][0], acc[nt][1]);
        *(float2*)&wh1[nt * 8 + 2 * tig] = make_float2(acc[nt][2], acc[nt][3]);
    }
}

// ---------------------------------------------------------------------------
// Attention: A-fragments of P computed directly in registers (no P smem).
// Wh staged in XOR-swizzled fragment layout: slot(k,gc) = gc ^ ((k&3)<<1),
// word index = k*64 + slot*8 + nt  ->  value Wh[j0+k][nt*8+gc].
// Adjacency via bitmask words (2 LDG.32 per thread per tile).
// ---------------------------------------------------------------------------
template<bool ELU, bool TO_GX>
__global__ __launch_bounds__(256) void attn_frag(float* __restrict__ out_ext)
{
    __shared__ __align__(16) float4 jtab[Nc];            // (s_j, e^{s_j}, e^{0.2 s_j}, -)
    __shared__ float sil[128], A1v[128], A2v[128], den[128], red[8];
    __shared__ __align__(16) uint32_t wsf[2][32 * 64];

    int tid = threadIdx.x, lane = tid & 31, wid = tid >> 5;
    int g = lane >> 2, tig = lane & 3, wr0 = wid * 16;
    int r0 = wr0 + g, r1 = r0 + 8;
    int bh = blockIdx.y, i0 = blockIdx.x * 128;

    const float* sjg = &g_sj[(size_t)bh * Nc];
    const float* sig = &g_si[(size_t)bh * Nc];

    // ---- Prologue ----
    float lmax = -3.0e38f;
    for (int j = tid; j < Nc; j += 256){ float v = sjg[j]; jtab[j].x = v; lmax = fmaxf(lmax, v); }
    #pragma unroll
    for (int o = 16; o; o >>= 1) lmax = fmaxf(lmax, __shfl_xor_sync(0xffffffffu, lmax, o));
    if (lane == 0) red[wid] = lmax;
    __syncthreads();
    float smax = red[0];
    #pragma unroll
    for (int w2 = 1; w2 < 8; w2++) smax = fmaxf(smax, red[w2]);
    for (int j = tid; j < Nc; j += 256){
        float v = jtab[j].x;
        jtab[j].y = expf(v); jtab[j].z = expf(0.2f * v);
    }
    if (tid < 128){
        float s = sig[i0 + tid]; sil[tid] = s;
        float e = s + smax; float m = e > 0.f ? e : 0.2f * e;   // exact row-max bound
        A1v[tid] = expf(s - m); A2v[tid] = expf(0.2f * s - m);
    }
    __syncthreads();

    float psil0 = sil[r0], pa10 = A1v[r0], pa20 = A2v[r0];
    float psil1 = sil[r1], pa11 = A1v[r1], pa21 = A2v[r1];
    const uint32_t* bits0 = &g_adjbits[(size_t)(i0 + r0) * 32];
    const uint32_t* bits1 = &g_adjbits[(size_t)(i0 + r1) * 32];

    // Wh staging: thread (sk, snt) covers row j0+sk, cols snt*8..snt*8+7.
    int sk = tid >> 3, snt = tid & 7;
    const float* wsrc = &g_Wh[((size_t)bh * Nc + sk) * Dc + snt * 8];
    int slot_w0 = ((sk & 3) << 1);   // gc ^ slot_w0

    float acc[8][4] = {};
    float d0 = 0.f, d1 = 0.f;

    // Pipeline prologue: stage tile 0, prefetch tile 1.
    float4 vaN, vbN;
    {
        float4 va = *(const float4*)&wsrc[0];
        float4 vb = *(const float4*)&wsrc[4];
        float v[8] = {va.x, va.y, va.z, va.w, vb.x, vb.y, vb.z, vb.w};
        #pragma unroll
        for (int gc = 0; gc < 8; gc++)
            wsf[0][sk * 64 + ((gc ^ slot_w0) << 3) + snt] = tf32u(v[gc]);
    }
    vaN = *(const float4*)&wsrc[(size_t)32 * Dc];
    vbN = *(const float4*)&wsrc[(size_t)32 * Dc + 4];
    uint32_t wA_c = bits0[0], wB_c = bits1[0];
    uint32_t wA_n = bits0[1], wB_n = bits1[1];
    __syncthreads();

    for (int t = 0; t < NTILE; t++){
        float4 va2 = make_float4(0,0,0,0), vb2 = va2;
        uint32_t wA2 = 0, wB2 = 0;
        if (t + 2 < NTILE){
            va2 = *(const float4*)&wsrc[(size_t)(t + 2) * 32 * Dc];
            vb2 = *(const float4*)&wsrc[(size_t)(t + 2) * 32 * Dc + 4];
            wA2 = bits0[t + 2]; wB2 = bits1[t + 2];
        }
        if (t + 1 < NTILE){
            float v[8] = {vaN.x, vaN.y, vaN.z, vaN.w, vbN.x, vbN.y, vbN.z, vbN.w};
            uint32_t* W = wsf[(t + 1) & 1];
            #pragma unroll
            for (int gc = 0; gc < 8; gc++)
                W[sk * 64 + ((gc ^ slot_w0) << 3) + snt] = tf32u(v[gc]);
        }
        // ---- compute tile t ----
        const uint32_t* W = wsf[t & 1];
        int slot_r = g ^ (tig << 1);
        #pragma unroll
        for (int ks = 0; ks < 4; ks++){
            int jb = t * 32 + ks * 8;
            float4 t0 = jtab[jb + tig];
            float4 t1 = jtab[jb + tig + 4];
            int sh = ks * 8 + tig;
            float p0 = (psil0 + t0.x > 0.f) ? pa10 * t0.y : pa20 * t0.z; if (!((wA_c >> sh) & 1))       p0 = 0.f;
            float p1 = (psil1 + t0.x > 0.f) ? pa11 * t0.y : pa21 * t0.z; if (!((wB_c >> sh) & 1))       p1 = 0.f;
            float p2 = (psil0 + t1.x > 0.f) ? pa10 * t1.y : pa20 * t1.z; if (!((wA_c >> (sh + 4)) & 1)) p2 = 0.f;
            float p3 = (psil1 + t1.x > 0.f) ? pa11 * t1.y : pa21 * t1.z; if (!((wB_c >> (sh + 4)) & 1)) p3 = 0.f;
            uint32_t a0 = tf32u(p0), a1 = tf32u(p1), a2 = tf32u(p2), a3 = tf32u(p3);
            d0 += __uint_as_float(a0) + __uint_as_float(a2);
            d1 += __uint_as_float(a1) + __uint_as_float(a3);
            const uint32_t* br0 = &W[ sh      * 64 + slot_r * 8];
            const uint32_t* br1 = &W[(sh + 4) * 64 + slot_r * 8];
            uint4 b00 = *(const uint4*)br0;
            uint4 b01 = *(const uint4*)(br0 + 4);
            uint4 b10 = *(const uint4*)br1;
            uint4 b11 = *(const uint4*)(br1 + 4);
            mma8(acc[0], a0, a1, a2, a3, b00.x, b10.x);
            mma8(acc[1], a0, a1, a2, a3, b00.y, b10.y);
            mma8(acc[2], a0, a1, a2, a3, b00.z, b10.z);
            mma8(acc[3], a0, a1, a2, a3, b00.w, b10.w);
            mma8(acc[4], a0, a1, a2, a3, b01.x, b11.x);
            mma8(acc[5], a0, a1, a2, a3, b01.y, b11.y);
            mma8(acc[6], a0, a1, a2, a3, b01.z, b11.z);
            mma8(acc[7], a0, a1, a2, a3, b01.w, b11.w);
        }
        vaN = va2; vbN = vb2;
        wA_c = wA_n; wB_c = wB_n; wA_n = wA2; wB_n = wB2;
        __syncthreads();
    }

    // Denominator: reduce over tig (lanes xor 1, 2 differ only in tig).
    d0 += __shfl_xor_sync(0xffffffffu, d0, 1); d0 += __shfl_xor_sync(0xffffffffu, d0, 2);
    d1 += __shfl_xor_sync(0xffffffffu, d1, 1); d1 += __shfl_xor_sync(0xffffffffu, d1, 2);
    if (tig == 0){ den[r0] = d0; den[r1] = d1; }
    __syncthreads();

    // Epilogue: normalize (+ELU), write concat layout.
    float inv0 = 1.f / den[r0];
    float inv1 = 1.f / den[r1];
    int b = bh / Hc, hh = bh % Hc;
    float* op = TO_GX ? (float*)g_x : out_ext;
    int n = i0 + r0;
    float* o0 = &op[(size_t)(b * Nc + n    ) * HIDc + hh * Dc];
    float* o1 = &op[(size_t)(b * Nc + n + 8) * HIDc + hh * Dc];
    #pragma unroll
    for (int nt = 0; nt < 8; nt++){
        float v00 = acc[nt][0] * inv0, v01 = acc[nt][1] * inv0;
        float v10 = acc[nt][2] * inv1, v11 = acc[nt][3] * inv1;
        if (ELU){
            v00 = v00 > 0.f ? v00 : expm1f(v00);
            v01 = v01 > 0.f ? v01 : expm1f(v01);
            v10 = v10 > 0.f ? v10 : expm1f(v10);
            v11 = v11 > 0.f ? v11 : expm1f(v11);
        }
        *(float2*)&o0[nt * 8 + 2 * tig] = make_float2(v00, v01);
        *(float2*)&o1[nt * 8 + 2 * tig] = make_float2(v10, v11);
    }
}

// ---------------------------------------------------------------------------
extern "C" void kernel_launch(void* const* d_in, const int* in_sizes, int n_in,
                              void* d_out, int out_size)
{
    const float* h   = (const float*)d_in[0];
    const float* adj = (const float*)d_in[1];
    const float* W1  = (const float*)d_in[2];
    const float* a1  = (const float*)d_in[3];
    const float* W2  = (const float*)d_in[4];
    const float* a2  = (const float*)d_in[5];
    float* out = (float*)d_out;

    dim3 projGrid(Bc * Nc / 128, Hc);   // (64, 3)
    dim3 attnGrid(Nc / 128, BHc);       // (8, 24)

    adjbits_kernel<<<(Nc * 32 * 32) / 256, 256>>>(adj);
    proj_mma<OBSc, false><<<projGrid, 256>>>(h, W1, a1);
    attn_frag<true,  true ><<<attnGrid, 256>>>(nullptr);
    proj_mma<HIDc, true ><<<projGrid, 256>>>(nullptr, W2, a2);
    attn_frag<false, false><<<attnGrid, 256>>>(out);
}